// round 2
// baseline (speedup 1.0000x reference)
#include <cuda_runtime.h>
#include <cuda_bf16.h>

#define N_NODES 50000
#define N_EDGES 800000
#define D_IN    128
#define D_HID   128
#define D_OUT   64

// -------- device scratch (allocation-free rule: __device__ globals) --------
__device__ float g_support[N_NODES * D_HID];
__device__ float g_h[N_NODES * D_HID];
__device__ int   g_row_ptr[N_NODES + 1];
__device__ int   g_counts[N_NODES];
__device__ int   g_cursor[N_NODES];
__device__ int   g_cols[N_EDGES];
__device__ float g_vals[N_EDGES];

// ---------------- packed f32x2 helpers (Blackwell FFMA2 path) --------------
__device__ __forceinline__ unsigned long long fma2(unsigned long long a,
                                                   unsigned long long b,
                                                   unsigned long long c) {
    unsigned long long d;
    asm("fma.rn.f32x2 %0, %1, %2, %3;" : "=l"(d) : "l"(a), "l"(b), "l"(c));
    return d;
}
__device__ __forceinline__ unsigned long long pack2(float lo, float hi) {
    unsigned long long d;
    asm("mov.b64 %0, {%1, %2};" : "=l"(d) : "f"(lo), "f"(hi));
    return d;
}
__device__ __forceinline__ float reduce2(unsigned long long p) {
    float lo, hi;
    asm("mov.b64 {%0, %1}, %2;" : "=f"(lo), "=f"(hi) : "l"(p));
    return lo + hi;
}

// ============================ CSR construction ==============================

__global__ void zero_kernel() {
    int i = blockIdx.x * blockDim.x + threadIdx.x;
    if (i < N_NODES) { g_counts[i] = 0; g_cursor[i] = 0; }
}

__global__ void hist_kernel(const int* __restrict__ edge_row) {
    int e = blockIdx.x * blockDim.x + threadIdx.x;
    if (e < N_EDGES) atomicAdd(&g_counts[edge_row[e]], 1);
}

// single-block exclusive scan, int4 per thread (4096 elems / iteration)
__global__ void scan_kernel() {
    __shared__ int warp_sums[32];
    __shared__ int carry_s;
    const int tid  = threadIdx.x;
    const int lane = tid & 31;
    const int wid  = tid >> 5;
    if (tid == 0) carry_s = 0;
    __syncthreads();
    const int4* c4 = (const int4*)g_counts;
    const int N4 = N_NODES / 4;   // 12500
    for (int base = 0; base < N4; base += 1024) {
        int i = base + tid;
        int4 v = (i < N4) ? c4[i] : make_int4(0, 0, 0, 0);
        int s = v.x + v.y + v.z + v.w;
        int incl = s;
        #pragma unroll
        for (int off = 1; off < 32; off <<= 1) {
            int t = __shfl_up_sync(0xffffffffu, incl, off);
            if (lane >= off) incl += t;
        }
        if (lane == 31) warp_sums[wid] = incl;
        __syncthreads();
        if (wid == 0) {
            int ws = warp_sums[lane];
            int wincl = ws;
            #pragma unroll
            for (int off = 1; off < 32; off <<= 1) {
                int t = __shfl_up_sync(0xffffffffu, wincl, off);
                if (lane >= off) wincl += t;
            }
            warp_sums[lane] = wincl - ws;   // exclusive warp prefix
        }
        __syncthreads();
        int carry = carry_s;
        int excl = carry + warp_sums[wid] + incl - s;
        if (i < N4) {
            int4 o;
            o.x = excl;
            o.y = excl + v.x;
            o.z = o.y + v.y;
            o.w = o.z + v.z;
            *(int4*)&g_row_ptr[4 * i] = o;
        }
        __syncthreads();
        if (tid == 1023) carry_s = carry + warp_sums[31] + incl;
        __syncthreads();
    }
    if (tid == 0) g_row_ptr[N_NODES] = carry_s;
}

__global__ void scatter_kernel(const int* __restrict__ edge_row,
                               const int* __restrict__ edge_col,
                               const float* __restrict__ edge_val) {
    int e = blockIdx.x * blockDim.x + threadIdx.x;
    if (e < N_EDGES) {
        int r = edge_row[e];
        int p = g_row_ptr[r] + atomicAdd(&g_cursor[r], 1);
        g_cols[p] = edge_col[e];
        g_vals[p] = edge_val[e];
    }
}

// ================================ GEMM ======================================
// C[N, NC] = A[N, 128] @ W[128, NC], fp32 via packed FFMA2 over k-pairs.
// Accumulators are f32x2: lo holds even-k partials, hi odd-k; reduced at end.

template <int NC>
__global__ void gemm_kernel(const float* __restrict__ A,
                            const float* __restrict__ W,
                            float* __restrict__ C, int N) {
    constexpr int K   = 128;
    constexpr int KC  = 64;
    constexpr int TM  = 64;
    constexpr int CPT = 4;
    constexpr int RPT = 8;
    constexpr int TC  = NC / CPT;         // 32 or 16
    constexpr int NT  = TC * (TM / RPT);  // 256 or 128

    __shared__ float W_s[KC][NC];
    __shared__ float A_s[TM][KC];

    const int tid  = threadIdx.x;
    const int cid  = tid % TC;
    const int rgrp = tid / TC;
    const int row0 = blockIdx.x * TM;

    unsigned long long acc[RPT][CPT];
    #pragma unroll
    for (int r = 0; r < RPT; r++)
        #pragma unroll
        for (int c = 0; c < CPT; c++) acc[r][c] = 0ull;

    for (int kc = 0; kc < K; kc += KC) {
        for (int i = tid * 4; i < KC * NC; i += NT * 4) {
            int ks = i / NC, c = i % NC;
            *(float4*)&W_s[ks][c] = *(const float4*)&W[(kc + ks) * NC + c];
        }
        for (int i = tid * 4; i < TM * KC; i += NT * 4) {
            int r = i / KC, kk = i % KC;
            int gr = row0 + r;
            float4 v = make_float4(0.f, 0.f, 0.f, 0.f);
            if (gr < N) v = *(const float4*)&A[(size_t)gr * K + kc + kk];
            *(float4*)&A_s[r][kk] = v;
        }
        __syncthreads();

        #pragma unroll
        for (int k = 0; k < KC; k += 2) {
            float4 w0 = *(const float4*)&W_s[k][cid * CPT];
            float4 w1 = *(const float4*)&W_s[k + 1][cid * CPT];
            unsigned long long wp0 = pack2(w0.x, w1.x);
            unsigned long long wp1 = pack2(w0.y, w1.y);
            unsigned long long wp2 = pack2(w0.z, w1.z);
            unsigned long long wp3 = pack2(w0.w, w1.w);
            #pragma unroll
            for (int r = 0; r < RPT; r++) {
                unsigned long long a2 =
                    *(const unsigned long long*)&A_s[rgrp * RPT + r][k];
                acc[r][0] = fma2(a2, wp0, acc[r][0]);
                acc[r][1] = fma2(a2, wp1, acc[r][1]);
                acc[r][2] = fma2(a2, wp2, acc[r][2]);
                acc[r][3] = fma2(a2, wp3, acc[r][3]);
            }
        }
        __syncthreads();
    }

    #pragma unroll
    for (int r = 0; r < RPT; r++) {
        int gr = row0 + rgrp * RPT + r;
        if (gr < N) {
            float4 o;
            o.x = reduce2(acc[r][0]);
            o.y = reduce2(acc[r][1]);
            o.z = reduce2(acc[r][2]);
            o.w = reduce2(acc[r][3]);
            *(float4*)&C[(size_t)gr * NC + cid * CPT] = o;
        }
    }
}

// ================================ SpMM ======================================

template <int D, bool RELU>
__global__ void spmm_kernel(const float* __restrict__ S,
                            const float* __restrict__ bias,
                            float* __restrict__ out, int N) {
    constexpr int F = D / 32;
    const int warp = (blockIdx.x * blockDim.x + threadIdx.x) >> 5;
    const int lane = threadIdx.x & 31;
    if (warp >= N) return;

    const int start = g_row_ptr[warp];
    const int end   = g_row_ptr[warp + 1];

    float acc[F];
    #pragma unroll
    for (int j = 0; j < F; j++) acc[j] = 0.0f;

    #pragma unroll 4
    for (int e = start; e < end; e++) {
        int   c = __ldg(&g_cols[e]);
        float v = __ldg(&g_vals[e]);
        if (F == 4) {
            float4 s = *(const float4*)&S[(size_t)c * D + lane * 4];
            acc[0] += v * s.x; acc[1] += v * s.y;
            acc[2] += v * s.z; acc[3] += v * s.w;
        } else {
            float2 s = *(const float2*)&S[(size_t)c * D + lane * 2];
            acc[0] += v * s.x; acc[1] += v * s.y;
        }
    }

    #pragma unroll
    for (int j = 0; j < F; j++) {
        float r = acc[j] + __ldg(&bias[lane * F + j]);
        if (RELU) r = fmaxf(r, 0.0f);
        acc[j] = r;
    }
    if (F == 4)
        *(float4*)&out[(size_t)warp * D + lane * 4] =
            make_float4(acc[0], acc[1], acc[2], acc[3]);
    else
        *(float2*)&out[(size_t)warp * D + lane * 2] =
            make_float2(acc[0], acc[1]);
}

// ============================== launch =====================================

extern "C" void kernel_launch(void* const* d_in, const int* in_sizes, int n_in,
                              void* d_out, int out_size) {
    const float* x        = (const float*)d_in[0];
    const int*   edge_row = (const int*)  d_in[1];
    const int*   edge_col = (const int*)  d_in[2];
    const float* edge_val = (const float*)d_in[3];
    const float* W1       = (const float*)d_in[4];
    const float* b1       = (const float*)d_in[5];
    const float* W2       = (const float*)d_in[6];
    const float* b2       = (const float*)d_in[7];
    const float* W3       = (const float*)d_in[8];
    const float* b3       = (const float*)d_in[9];
    float* out = (float*)d_out;

    const int N = N_NODES;
    const int E = N_EDGES;

    zero_kernel<<<(N + 255) / 256, 256>>>();
    hist_kernel<<<(E + 255) / 256, 256>>>(edge_row);
    scan_kernel<<<1, 1024>>>();
    scatter_kernel<<<(E + 255) / 256, 256>>>(edge_row, edge_col, edge_val);

    float* support; cudaGetSymbolAddress((void**)&support, g_support);
    float* h;       cudaGetSymbolAddress((void**)&h, g_h);

    const int gemm_grid = (N + 63) / 64;
    const int spmm_grid = (N + 7) / 8;

    gemm_kernel<128><<<gemm_grid, 256>>>(x, W1, support, N);
    spmm_kernel<128, true><<<spmm_grid, 256>>>(support, b1, h, N);

    gemm_kernel<128><<<gemm_grid, 256>>>(h, W2, support, N);
    spmm_kernel<128, true><<<spmm_grid, 256>>>(support, b2, h, N);

    gemm_kernel<64><<<gemm_grid, 128>>>(h, W3, support, N);
    spmm_kernel<64, false><<<spmm_grid, 256>>>(support, b3, out, N);
}

// round 4
// speedup vs baseline: 1.3214x; 1.3214x over previous
#include <cuda_runtime.h>
#include <cuda_fp16.h>
#include <cstdint>

#define N_NODES 50000
#define N_EDGES 800000
#define D_IN    128
#define D_HID   128
#define D_OUT   64

// -------- device scratch (allocation-free rule: __device__ globals) --------
__device__ float g_support[N_NODES * D_HID];
__device__ float g_h[N_NODES * D_HID];
__device__ int   g_row_ptr[N_NODES + 1];
__device__ int   g_counts[N_NODES];
__device__ int   g_cursor[N_NODES];
__device__ int   g_cols[N_EDGES];
__device__ float g_vals[N_EDGES];

// W images: fp16 hi/lo, W^T layout [n][k] with rows padded to 136 halfs.
// layer1 hi+lo (2*128*136), layer2 hi+lo (2*128*136), layer3 hi+lo (2*64*136)
#define WROW 136
__device__ __align__(16) half g_wimg[2 * 128 * WROW + 2 * 128 * WROW + 2 * 64 * WROW];

// ============================ CSR construction ==============================

__global__ void zero_kernel() {
    int i = blockIdx.x * blockDim.x + threadIdx.x;
    if (i < N_NODES) g_counts[i] = 0;
}

__global__ void hist_kernel(const int* __restrict__ edge_row) {
    int e = blockIdx.x * blockDim.x + threadIdx.x;
    if (e < N_EDGES) atomicAdd(&g_counts[edge_row[e]], 1);
}

// single-block exclusive scan, int4 per thread; also seeds g_cursor = row_ptr
__global__ void scan_kernel() {
    __shared__ int warp_sums[32];
    __shared__ int carry_s;
    const int tid  = threadIdx.x;
    const int lane = tid & 31;
    const int wid  = tid >> 5;
    if (tid == 0) carry_s = 0;
    __syncthreads();
    const int4* c4 = (const int4*)g_counts;
    const int N4 = N_NODES / 4;
    for (int base = 0; base < N4; base += 1024) {
        int i = base + tid;
        int4 v = (i < N4) ? c4[i] : make_int4(0, 0, 0, 0);
        int s = v.x + v.y + v.z + v.w;
        int incl = s;
        #pragma unroll
        for (int off = 1; off < 32; off <<= 1) {
            int t = __shfl_up_sync(0xffffffffu, incl, off);
            if (lane >= off) incl += t;
        }
        if (lane == 31) warp_sums[wid] = incl;
        __syncthreads();
        if (wid == 0) {
            int ws = warp_sums[lane];
            int wincl = ws;
            #pragma unroll
            for (int off = 1; off < 32; off <<= 1) {
                int t = __shfl_up_sync(0xffffffffu, wincl, off);
                if (lane >= off) wincl += t;
            }
            warp_sums[lane] = wincl - ws;
        }
        __syncthreads();
        int carry = carry_s;
        int excl = carry + warp_sums[wid] + incl - s;
        if (i < N4) {
            int4 o;
            o.x = excl;
            o.y = excl + v.x;
            o.z = o.y + v.y;
            o.w = o.z + v.z;
            *(int4*)&g_row_ptr[4 * i] = o;
            *(int4*)&g_cursor[4 * i]  = o;
        }
        __syncthreads();
        if (tid == 1023) carry_s = carry + warp_sums[31] + incl;
        __syncthreads();
    }
    if (tid == 0) g_row_ptr[N_NODES] = carry_s;
}

__global__ void scatter_kernel(const int* __restrict__ edge_row,
                               const int* __restrict__ edge_col,
                               const float* __restrict__ edge_val) {
    int e = blockIdx.x * blockDim.x + threadIdx.x;
    if (e < N_EDGES) {
        int r = edge_row[e];
        int p = atomicAdd(&g_cursor[r], 1);
        g_cols[p] = edge_col[e];
        g_vals[p] = edge_val[e];
    }
}

// ====================== W image prep (fp16 split, W^T padded) ===============
// W: [128, NC] row-major (W[k*NC+n]) -> img_hi[n][k], img_lo[n][k], rows WROW.

__global__ void prep_w_kernel(const float* __restrict__ W, half* __restrict__ img,
                              int NC) {
    int idx = blockIdx.x * blockDim.x + threadIdx.x;
    if (idx >= 128 * NC) return;
    int k = idx / NC;
    int n = idx % NC;
    float v = W[idx];
    half hi = __float2half_rn(v);
    half lo = __float2half_rn(v - __half2float(hi));
    img[n * WROW + k] = hi;
    img[NC * WROW + n * WROW + k] = lo;
}

// ============================ HMMA GEMM =====================================
// C[M, NC] = A[M,128] @ W[128,NC] via mma.sync.m16n8k16 f16->f32, 3-term split:
// Ah*Bh + Ah*Bl + Al*Bh. 256 threads, tile = 128 rows; warp = one m16 band.

__device__ __forceinline__ void mma16816(float* d,
                                         uint32_t a0, uint32_t a1, uint32_t a2, uint32_t a3,
                                         uint32_t b0, uint32_t b1) {
    asm volatile(
        "mma.sync.aligned.m16n8k16.row.col.f32.f16.f16.f32 "
        "{%0,%1,%2,%3}, {%4,%5,%6,%7}, {%8,%9}, {%0,%1,%2,%3};"
        : "+f"(d[0]), "+f"(d[1]), "+f"(d[2]), "+f"(d[3])
        : "r"(a0), "r"(a1), "r"(a2), "r"(a3), "r"(b0), "r"(b1));
}

template <int NC>
__global__ void __launch_bounds__(256, 1)
gemm_mma_kernel(const float* __restrict__ A, const half* __restrict__ Wimg,
                float* __restrict__ C, int M) {
    extern __shared__ __align__(16) char smem_raw[];
    half* Wh = (half*)smem_raw;              // [NC][WROW]
    half* Wl = Wh + NC * WROW;               // [NC][WROW]
    half* Ah = Wl + NC * WROW;               // [128][WROW]
    half* Al = Ah + 128 * WROW;              // [128][WROW]

    const int tid = threadIdx.x;

    // copy W hi+lo images (contiguous in gmem) into smem
    {
        const uint4* src = (const uint4*)Wimg;
        uint4* dst = (uint4*)Wh;
        constexpr int n16 = 2 * NC * WROW * 2 / 16;   // NC*34
        #pragma unroll 4
        for (int i = tid; i < n16; i += 256) dst[i] = src[i];
    }

    // load A tile (128x128 fp32), split to fp16 hi/lo in smem
    {
        const int r  = tid >> 1;
        const int c0 = (tid & 1) * 64;
        const int gr = blockIdx.x * 128 + r;
        const bool valid = (gr < M);
        const float4* src = (const float4*)(A + (size_t)gr * 128 + c0);
        #pragma unroll
        for (int j = 0; j < 16; j++) {
            float4 v = valid ? src[j] : make_float4(0.f, 0.f, 0.f, 0.f);
            half hx = __float2half_rn(v.x), hy = __float2half_rn(v.y);
            half hz = __float2half_rn(v.z), hw = __float2half_rn(v.w);
            half lx = __float2half_rn(v.x - __half2float(hx));
            half ly = __float2half_rn(v.y - __half2float(hy));
            half lz = __float2half_rn(v.z - __half2float(hz));
            half lw = __float2half_rn(v.w - __half2float(hw));
            int base = r * WROW + c0 + j * 4;
            *(half2*)&Ah[base]     = __halves2half2(hx, hy);
            *(half2*)&Ah[base + 2] = __halves2half2(hz, hw);
            *(half2*)&Al[base]     = __halves2half2(lx, ly);
            *(half2*)&Al[base + 2] = __halves2half2(lz, lw);
        }
    }
    __syncthreads();

    const int warp = tid >> 5;
    const int lane = tid & 31;
    const int qr = lane >> 2;          // 0..7
    const int qc = (lane & 3) * 2;     // 0,2,4,6
    const int mrow = warp * 16;

    constexpr int NT = NC / 8;
    float acc[NT][4];
    #pragma unroll
    for (int nt = 0; nt < NT; nt++)
        #pragma unroll
        for (int j = 0; j < 4; j++) acc[nt][j] = 0.f;

    #pragma unroll
    for (int ks = 0; ks < 8; ks++) {
        const int kb = ks * 16 + qc;
        const int ra = (mrow + qr) * WROW + kb;
        const int rb = (mrow + qr + 8) * WROW + kb;
        uint32_t ah0 = *(const uint32_t*)&Ah[ra];
        uint32_t ah1 = *(const uint32_t*)&Ah[rb];
        uint32_t ah2 = *(const uint32_t*)&Ah[ra + 8];
        uint32_t ah3 = *(const uint32_t*)&Ah[rb + 8];
        uint32_t al0 = *(const uint32_t*)&Al[ra];
        uint32_t al1 = *(const uint32_t*)&Al[rb];
        uint32_t al2 = *(const uint32_t*)&Al[ra + 8];
        uint32_t al3 = *(const uint32_t*)&Al[rb + 8];
        #pragma unroll
        for (int nt = 0; nt < NT; nt++) {
            const int nr = (nt * 8 + qr) * WROW + kb;
            uint32_t bh0 = *(const uint32_t*)&Wh[nr];
            uint32_t bh1 = *(const uint32_t*)&Wh[nr + 8];
            uint32_t bl0 = *(const uint32_t*)&Wl[nr];
            uint32_t bl1 = *(const uint32_t*)&Wl[nr + 8];
            mma16816(acc[nt], ah0, ah1, ah2, ah3, bh0, bh1);
            mma16816(acc[nt], ah0, ah1, ah2, ah3, bl0, bl1);
            mma16816(acc[nt], al0, al1, al2, al3, bh0, bh1);
        }
    }

    // epilogue: C frag rows = mrow+qr (+8), cols = nt*8 + qc (+1)
    const int grow = blockIdx.x * 128 + mrow + qr;
    #pragma unroll
    for (int nt = 0; nt < NT; nt++) {
        const int col = nt * 8 + qc;
        if (grow < M)
            *(float2*)&C[(size_t)grow * NC + col] = make_float2(acc[nt][0], acc[nt][1]);
        if (grow + 8 < M)
            *(float2*)&C[(size_t)(grow + 8) * NC + col] = make_float2(acc[nt][2], acc[nt][3]);
    }
}

// ================================ SpMM ======================================

template <int D, bool RELU>
__global__ void spmm_kernel(const float* __restrict__ S,
                            const float* __restrict__ bias,
                            float* __restrict__ out, int N) {
    constexpr int F = D / 32;
    const int warp = (blockIdx.x * blockDim.x + threadIdx.x) >> 5;
    const int lane = threadIdx.x & 31;
    if (warp >= N) return;

    const int start = g_row_ptr[warp];
    const int end   = g_row_ptr[warp + 1];

    float acc[F];
    #pragma unroll
    for (int j = 0; j < F; j++) acc[j] = 0.0f;

    #pragma unroll 4
    for (int e = start; e < end; e++) {
        int   c = __ldg(&g_cols[e]);
        float v = __ldg(&g_vals[e]);
        if (F == 4) {
            float4 s = *(const float4*)&S[(size_t)c * D + lane * 4];
            acc[0] += v * s.x; acc[1] += v * s.y;
            acc[2] += v * s.z; acc[3] += v * s.w;
        } else {
            float2 s = *(const float2*)&S[(size_t)c * D + lane * 2];
            acc[0] += v * s.x; acc[1] += v * s.y;
        }
    }

    #pragma unroll
    for (int j = 0; j < F; j++) {
        float r = acc[j] + __ldg(&bias[lane * F + j]);
        if (RELU) r = fmaxf(r, 0.0f);
        acc[j] = r;
    }
    if (F == 4)
        *(float4*)&out[(size_t)warp * D + lane * 4] =
            make_float4(acc[0], acc[1], acc[2], acc[3]);
    else
        *(float2*)&out[(size_t)warp * D + lane * 2] =
            make_float2(acc[0], acc[1]);
}

// ============================== launch =====================================

extern "C" void kernel_launch(void* const* d_in, const int* in_sizes, int n_in,
                              void* d_out, int out_size) {
    const float* x        = (const float*)d_in[0];
    const int*   edge_row = (const int*)  d_in[1];
    const int*   edge_col = (const int*)  d_in[2];
    const float* edge_val = (const float*)d_in[3];
    const float* W1       = (const float*)d_in[4];
    const float* b1       = (const float*)d_in[5];
    const float* W2       = (const float*)d_in[6];
    const float* b2       = (const float*)d_in[7];
    const float* W3       = (const float*)d_in[8];
    const float* b3       = (const float*)d_in[9];
    float* out = (float*)d_out;

    const int N = N_NODES;
    const int E = N_EDGES;

    float* support; cudaGetSymbolAddress((void**)&support, g_support);
    float* h;       cudaGetSymbolAddress((void**)&h, g_h);
    half*  wimg;    cudaGetSymbolAddress((void**)&wimg, g_wimg);
    half* wimg1 = wimg;
    half* wimg2 = wimg + 2 * 128 * WROW;
    half* wimg3 = wimg + 4 * 128 * WROW;

    const int SMEM_128 = (2 * 128 * WROW + 2 * 128 * WROW) * 2;  // 139264
    const int SMEM_64  = (2 * 64  * WROW + 2 * 128 * WROW) * 2;  // 104448
    static bool attr_done = false;
    cudaFuncSetAttribute(gemm_mma_kernel<128>,
                         cudaFuncAttributeMaxDynamicSharedMemorySize, SMEM_128);
    cudaFuncSetAttribute(gemm_mma_kernel<64>,
                         cudaFuncAttributeMaxDynamicSharedMemorySize, SMEM_64);
    (void)attr_done;

    // W image prep + CSR build
    prep_w_kernel<<<(128 * 128 + 255) / 256, 256>>>(W1, wimg1, 128);
    prep_w_kernel<<<(128 * 128 + 255) / 256, 256>>>(W2, wimg2, 128);
    prep_w_kernel<<<(128 * 64 + 255) / 256, 256>>>(W3, wimg3, 64);
    zero_kernel<<<(N + 255) / 256, 256>>>();
    hist_kernel<<<(E + 255) / 256, 256>>>(edge_row);
    scan_kernel<<<1, 1024>>>();
    scatter_kernel<<<(E + 255) / 256, 256>>>(edge_row, edge_col, edge_val);

    const int gemm_grid = (N + 127) / 128;   // 391
    const int spmm_grid = (N + 7) / 8;

    gemm_mma_kernel<128><<<gemm_grid, 256, SMEM_128>>>(x, wimg1, support, N);
    spmm_kernel<128, true><<<spmm_grid, 256>>>(support, b1, h, N);

    gemm_mma_kernel<128><<<gemm_grid, 256, SMEM_128>>>(h, wimg2, support, N);
    spmm_kernel<128, true><<<spmm_grid, 256>>>(support, b2, h, N);

    gemm_mma_kernel<64><<<gemm_grid, 256, SMEM_64>>>(h, wimg3, support, N);
    spmm_kernel<64, false><<<spmm_grid, 256>>>(support, b3, out, N);
}

// round 5
// speedup vs baseline: 1.4312x; 1.0831x over previous
#include <cuda_runtime.h>
#include <cuda_fp16.h>
#include <cstdint>

#define N_NODES 50000
#define N_EDGES 800000
#define D_IN    128
#define D_HID   128
#define D_OUT   64

// -------- device scratch (allocation-free rule: __device__ globals) --------
__device__ __align__(16) half g_support[N_NODES * D_HID];  // GEMM out (fp16)
__device__ float g_h[N_NODES * D_HID];                     // activations (fp32)
__device__ int   g_row_ptr[N_NODES + 1];
__device__ int   g_counts[N_NODES];
__device__ int   g_cursor[N_NODES];
__device__ __align__(16) uint2 g_edge[N_EDGES];            // (col, val) packed

// W images: fp16 hi/lo, W^T layout [n][k] with rows padded to 136 halfs.
#define WROW 136
__device__ __align__(16) half g_wimg[2 * 128 * WROW + 2 * 128 * WROW + 2 * 64 * WROW];

// ============================ CSR construction ==============================

__global__ void hist_kernel(const int* __restrict__ edge_row) {
    int e = blockIdx.x * blockDim.x + threadIdx.x;
    if (e < N_EDGES) atomicAdd(&g_counts[edge_row[e]], 1);
}

// single-block exclusive scan, int4 per thread; also seeds g_cursor = row_ptr
__global__ void scan_kernel() {
    __shared__ int warp_sums[32];
    __shared__ int carry_s;
    const int tid  = threadIdx.x;
    const int lane = tid & 31;
    const int wid  = tid >> 5;
    if (tid == 0) carry_s = 0;
    __syncthreads();
    const int4* c4 = (const int4*)g_counts;
    const int N4 = N_NODES / 4;
    for (int base = 0; base < N4; base += 1024) {
        int i = base + tid;
        int4 v = (i < N4) ? c4[i] : make_int4(0, 0, 0, 0);
        int s = v.x + v.y + v.z + v.w;
        int incl = s;
        #pragma unroll
        for (int off = 1; off < 32; off <<= 1) {
            int t = __shfl_up_sync(0xffffffffu, incl, off);
            if (lane >= off) incl += t;
        }
        if (lane == 31) warp_sums[wid] = incl;
        __syncthreads();
        if (wid == 0) {
            int ws = warp_sums[lane];
            int wincl = ws;
            #pragma unroll
            for (int off = 1; off < 32; off <<= 1) {
                int t = __shfl_up_sync(0xffffffffu, wincl, off);
                if (lane >= off) wincl += t;
            }
            warp_sums[lane] = wincl - ws;
        }
        __syncthreads();
        int carry = carry_s;
        int excl = carry + warp_sums[wid] + incl - s;
        if (i < N4) {
            int4 o;
            o.x = excl;
            o.y = excl + v.x;
            o.z = o.y + v.y;
            o.w = o.z + v.z;
            *(int4*)&g_row_ptr[4 * i] = o;
            *(int4*)&g_cursor[4 * i]  = o;
        }
        __syncthreads();
        if (tid == 1023) carry_s = carry + warp_sums[31] + incl;
        __syncthreads();
    }
    if (tid == 0) g_row_ptr[N_NODES] = carry_s;
}

__global__ void scatter_kernel(const int* __restrict__ edge_row,
                               const int* __restrict__ edge_col,
                               const float* __restrict__ edge_val) {
    int e = blockIdx.x * blockDim.x + threadIdx.x;
    if (e < N_EDGES) {
        int r = edge_row[e];
        int p = atomicAdd(&g_cursor[r], 1);
        g_edge[p] = make_uint2((uint32_t)edge_col[e], __float_as_uint(edge_val[e]));
    }
}

// ====================== W image prep (fp16 split, W^T padded) ===============
// W: [128, NC] row-major -> img_hi[n][k], img_lo[n][k], rows WROW.
// zero_counts: also grid-stride clear g_counts (fused zero_kernel).

__global__ void prep_w_kernel(const float* __restrict__ W, half* __restrict__ img,
                              int NC, int zero_counts) {
    int idx = blockIdx.x * blockDim.x + threadIdx.x;
    if (zero_counts) {
        for (int i = idx; i < N_NODES; i += gridDim.x * blockDim.x)
            g_counts[i] = 0;
    }
    if (idx >= 128 * NC) return;
    int k = idx / NC;
    int n = idx % NC;
    float v = W[idx];
    half hi = __float2half_rn(v);
    half lo = __float2half_rn(v - __half2float(hi));
    img[n * WROW + k] = hi;
    img[NC * WROW + n * WROW + k] = lo;
}

// ============================ HMMA GEMM =====================================
// C[M, NC](fp16) = A[M,128](fp32) @ W[128,NC] via m16n8k16 f16->f32, 3 terms.

__device__ __forceinline__ void mma16816(float* d,
                                         uint32_t a0, uint32_t a1, uint32_t a2, uint32_t a3,
                                         uint32_t b0, uint32_t b1) {
    asm volatile(
        "mma.sync.aligned.m16n8k16.row.col.f32.f16.f16.f32 "
        "{%0,%1,%2,%3}, {%4,%5,%6,%7}, {%8,%9}, {%0,%1,%2,%3};"
        : "+f"(d[0]), "+f"(d[1]), "+f"(d[2]), "+f"(d[3])
        : "r"(a0), "r"(a1), "r"(a2), "r"(a3), "r"(b0), "r"(b1));
}

template <int NC>
__global__ void __launch_bounds__(256, 1)
gemm_mma_kernel(const float* __restrict__ A, const half* __restrict__ Wimg,
                half* __restrict__ C, int M) {
    extern __shared__ __align__(16) char smem_raw[];
    half* Wh = (half*)smem_raw;              // [NC][WROW]
    half* Wl = Wh + NC * WROW;
    half* Ah = Wl + NC * WROW;               // [128][WROW]
    half* Al = Ah + 128 * WROW;

    const int tid = threadIdx.x;

    {
        const uint4* src = (const uint4*)Wimg;
        uint4* dst = (uint4*)Wh;
        constexpr int n16 = 2 * NC * WROW * 2 / 16;
        #pragma unroll 4
        for (int i = tid; i < n16; i += 256) dst[i] = src[i];
    }

    {
        const int r  = tid >> 1;
        const int c0 = (tid & 1) * 64;
        const int gr = blockIdx.x * 128 + r;
        const bool valid = (gr < M);
        const float4* src = (const float4*)(A + (size_t)gr * 128 + c0);
        #pragma unroll
        for (int j = 0; j < 16; j++) {
            float4 v = valid ? src[j] : make_float4(0.f, 0.f, 0.f, 0.f);
            half hx = __float2half_rn(v.x), hy = __float2half_rn(v.y);
            half hz = __float2half_rn(v.z), hw = __float2half_rn(v.w);
            half lx = __float2half_rn(v.x - __half2float(hx));
            half ly = __float2half_rn(v.y - __half2float(hy));
            half lz = __float2half_rn(v.z - __half2float(hz));
            half lw = __float2half_rn(v.w - __half2float(hw));
            int base = r * WROW + c0 + j * 4;
            *(half2*)&Ah[base]     = __halves2half2(hx, hy);
            *(half2*)&Ah[base + 2] = __halves2half2(hz, hw);
            *(half2*)&Al[base]     = __halves2half2(lx, ly);
            *(half2*)&Al[base + 2] = __halves2half2(lz, lw);
        }
    }
    __syncthreads();

    const int warp = tid >> 5;
    const int lane = tid & 31;
    const int qr = lane >> 2;
    const int qc = (lane & 3) * 2;
    const int mrow = warp * 16;

    constexpr int NT = NC / 8;
    float acc[NT][4];
    #pragma unroll
    for (int nt = 0; nt < NT; nt++)
        #pragma unroll
        for (int j = 0; j < 4; j++) acc[nt][j] = 0.f;

    #pragma unroll
    for (int ks = 0; ks < 8; ks++) {
        const int kb = ks * 16 + qc;
        const int ra = (mrow + qr) * WROW + kb;
        const int rb = (mrow + qr + 8) * WROW + kb;
        uint32_t ah0 = *(const uint32_t*)&Ah[ra];
        uint32_t ah1 = *(const uint32_t*)&Ah[rb];
        uint32_t ah2 = *(const uint32_t*)&Ah[ra + 8];
        uint32_t ah3 = *(const uint32_t*)&Ah[rb + 8];
        uint32_t al0 = *(const uint32_t*)&Al[ra];
        uint32_t al1 = *(const uint32_t*)&Al[rb];
        uint32_t al2 = *(const uint32_t*)&Al[ra + 8];
        uint32_t al3 = *(const uint32_t*)&Al[rb + 8];
        #pragma unroll
        for (int nt = 0; nt < NT; nt++) {
            const int nr = (nt * 8 + qr) * WROW + kb;
            uint32_t bh0 = *(const uint32_t*)&Wh[nr];
            uint32_t bh1 = *(const uint32_t*)&Wh[nr + 8];
            uint32_t bl0 = *(const uint32_t*)&Wl[nr];
            uint32_t bl1 = *(const uint32_t*)&Wl[nr + 8];
            mma16816(acc[nt], ah0, ah1, ah2, ah3, bh0, bh1);
            mma16816(acc[nt], ah0, ah1, ah2, ah3, bl0, bl1);
            mma16816(acc[nt], al0, al1, al2, al3, bh0, bh1);
        }
    }

    const int grow = blockIdx.x * 128 + mrow + qr;
    #pragma unroll
    for (int nt = 0; nt < NT; nt++) {
        const int col = nt * 8 + qc;
        if (grow < M)
            *(half2*)&C[(size_t)grow * NC + col] =
                __floats2half2_rn(acc[nt][0], acc[nt][1]);
        if (grow + 8 < M)
            *(half2*)&C[(size_t)(grow + 8) * NC + col] =
                __floats2half2_rn(acc[nt][2], acc[nt][3]);
    }
}

// ================================ SpMM ======================================
// warp-per-row segmented sum over packed CSR edges; fp16 gathers, fp32 acc.

template <int D, bool RELU>
__global__ void spmm_kernel(const half* __restrict__ S,
                            const float* __restrict__ bias,
                            float* __restrict__ out, int N) {
    constexpr int F = D / 32;                 // 4 or 2 halfs per lane
    const int warp = (blockIdx.x * blockDim.x + threadIdx.x) >> 5;
    const int lane = threadIdx.x & 31;
    if (warp >= N) return;

    const int start = g_row_ptr[warp];
    const int end   = g_row_ptr[warp + 1];

    float acc[F];
    #pragma unroll
    for (int j = 0; j < F; j++) acc[j] = 0.0f;

    #pragma unroll 4
    for (int e = start; e < end; e++) {
        uint2 pr = __ldg(&g_edge[e]);
        int   c = (int)pr.x;
        float v = __uint_as_float(pr.y);
        if (F == 4) {
            uint2 p = *(const uint2*)&S[(size_t)c * D + lane * 4];
            float2 f0 = __half22float2(*(half2*)&p.x);
            float2 f1 = __half22float2(*(half2*)&p.y);
            acc[0] += v * f0.x; acc[1] += v * f0.y;
            acc[2] += v * f1.x; acc[3] += v * f1.y;
        } else {
            uint32_t p = *(const uint32_t*)&S[(size_t)c * D + lane * 2];
            float2 f0 = __half22float2(*(half2*)&p);
            acc[0] += v * f0.x; acc[1] += v * f0.y;
        }
    }

    #pragma unroll
    for (int j = 0; j < F; j++) {
        float r = acc[j] + __ldg(&bias[lane * F + j]);
        if (RELU) r = fmaxf(r, 0.0f);
        acc[j] = r;
    }
    if (F == 4)
        *(float4*)&out[(size_t)warp * D + lane * 4] =
            make_float4(acc[0], acc[1], acc[2], acc[3]);
    else
        *(float2*)&out[(size_t)warp * D + lane * 2] =
            make_float2(acc[0], acc[1]);
}

// ============================== launch =====================================

extern "C" void kernel_launch(void* const* d_in, const int* in_sizes, int n_in,
                              void* d_out, int out_size) {
    const float* x        = (const float*)d_in[0];
    const int*   edge_row = (const int*)  d_in[1];
    const int*   edge_col = (const int*)  d_in[2];
    const float* edge_val = (const float*)d_in[3];
    const float* W1       = (const float*)d_in[4];
    const float* b1       = (const float*)d_in[5];
    const float* W2       = (const float*)d_in[6];
    const float* b2       = (const float*)d_in[7];
    const float* W3       = (const float*)d_in[8];
    const float* b3       = (const float*)d_in[9];
    float* out = (float*)d_out;

    const int N = N_NODES;
    const int E = N_EDGES;

    half*  support; cudaGetSymbolAddress((void**)&support, g_support);
    float* h;       cudaGetSymbolAddress((void**)&h, g_h);
    half*  wimg;    cudaGetSymbolAddress((void**)&wimg, g_wimg);
    half* wimg1 = wimg;
    half* wimg2 = wimg + 2 * 128 * WROW;
    half* wimg3 = wimg + 4 * 128 * WROW;

    const int SMEM_128 = (2 * 128 * WROW + 2 * 128 * WROW) * 2;  // 139264
    const int SMEM_64  = (2 * 64  * WROW + 2 * 128 * WROW) * 2;  // 104448
    cudaFuncSetAttribute(gemm_mma_kernel<128>,
                         cudaFuncAttributeMaxDynamicSharedMemorySize, SMEM_128);
    cudaFuncSetAttribute(gemm_mma_kernel<64>,
                         cudaFuncAttributeMaxDynamicSharedMemorySize, SMEM_64);

    // W image prep (first launch also zeroes g_counts) + CSR build
    prep_w_kernel<<<(128 * 128 + 255) / 256, 256>>>(W1, wimg1, 128, 1);
    prep_w_kernel<<<(128 * 128 + 255) / 256, 256>>>(W2, wimg2, 128, 0);
    prep_w_kernel<<<(128 * 64 + 255) / 256, 256>>>(W3, wimg3, 64, 0);
    hist_kernel<<<(E + 255) / 256, 256>>>(edge_row);
    scan_kernel<<<1, 1024>>>();
    scatter_kernel<<<(E + 255) / 256, 256>>>(edge_row, edge_col, edge_val);

    const int gemm_grid = (N + 127) / 128;   // 391
    const int spmm_grid = (N + 7) / 8;

    gemm_mma_kernel<128><<<gemm_grid, 256, SMEM_128>>>(x, wimg1, support, N);
    spmm_kernel<128, true><<<spmm_grid, 256>>>(support, b1, h, N);

    gemm_mma_kernel<128><<<gemm_grid, 256, SMEM_128>>>(h, wimg2, support, N);
    spmm_kernel<128, true><<<spmm_grid, 256>>>(support, b2, h, N);

    gemm_mma_kernel<64><<<gemm_grid, 256, SMEM_64>>>(h, wimg3, support, N);
    spmm_kernel<64, false><<<spmm_grid, 256>>>(support, b3, out, N);
}

// round 6
// speedup vs baseline: 1.6234x; 1.1343x over previous
#include <cuda_runtime.h>
#include <cuda_fp16.h>
#include <cstdint>

#define N_NODES 50000
#define N_EDGES 800000
#define D_IN    128
#define D_HID   128
#define D_OUT   64

// -------- device scratch (allocation-free rule: __device__ globals) --------
__device__ __align__(16) half g_support[N_NODES * D_HID];  // GEMM out (fp16)
__device__ __align__(16) half g_h[N_NODES * D_HID];        // activations (fp16)
__device__ int   g_row_ptr[N_NODES + 1];
__device__ int   g_counts[N_NODES];
__device__ int   g_cursor[N_NODES];
__device__ __align__(16) uint2 g_edge[N_EDGES];            // (col, val) packed

// W images: fp16 hi/lo, W^T layout [n][k] with rows padded to 136 halfs.
#define WROW 136
__device__ __align__(16) half g_wimg[2 * 128 * WROW + 2 * 128 * WROW + 2 * 64 * WROW];

// ============================ CSR construction ==============================

__global__ void hist_kernel(const int* __restrict__ edge_row) {
    int i = blockIdx.x * blockDim.x + threadIdx.x;      // i < E/4
    if (i < N_EDGES / 4) {
        int4 r = ((const int4*)edge_row)[i];
        atomicAdd(&g_counts[r.x], 1);
        atomicAdd(&g_counts[r.y], 1);
        atomicAdd(&g_counts[r.z], 1);
        atomicAdd(&g_counts[r.w], 1);
    }
}

// single-block exclusive scan, int4 per thread; also seeds g_cursor = row_ptr
__global__ void scan_kernel() {
    __shared__ int warp_sums[32];
    __shared__ int carry_s;
    const int tid  = threadIdx.x;
    const int lane = tid & 31;
    const int wid  = tid >> 5;
    if (tid == 0) carry_s = 0;
    __syncthreads();
    const int4* c4 = (const int4*)g_counts;
    const int N4 = N_NODES / 4;
    for (int base = 0; base < N4; base += 1024) {
        int i = base + tid;
        int4 v = (i < N4) ? c4[i] : make_int4(0, 0, 0, 0);
        int s = v.x + v.y + v.z + v.w;
        int incl = s;
        #pragma unroll
        for (int off = 1; off < 32; off <<= 1) {
            int t = __shfl_up_sync(0xffffffffu, incl, off);
            if (lane >= off) incl += t;
        }
        if (lane == 31) warp_sums[wid] = incl;
        __syncthreads();
        if (wid == 0) {
            int ws = warp_sums[lane];
            int wincl = ws;
            #pragma unroll
            for (int off = 1; off < 32; off <<= 1) {
                int t = __shfl_up_sync(0xffffffffu, wincl, off);
                if (lane >= off) wincl += t;
            }
            warp_sums[lane] = wincl - ws;
        }
        __syncthreads();
        int carry = carry_s;
        int excl = carry + warp_sums[wid] + incl - s;
        if (i < N4) {
            int4 o;
            o.x = excl;
            o.y = excl + v.x;
            o.z = o.y + v.y;
            o.w = o.z + v.z;
            *(int4*)&g_row_ptr[4 * i] = o;
            *(int4*)&g_cursor[4 * i]  = o;
        }
        __syncthreads();
        if (tid == 1023) carry_s = carry + warp_sums[31] + incl;
        __syncthreads();
    }
    if (tid == 0) g_row_ptr[N_NODES] = carry_s;
}

__global__ void scatter_kernel(const int* __restrict__ edge_row,
                               const int* __restrict__ edge_col,
                               const float* __restrict__ edge_val) {
    int i = blockIdx.x * blockDim.x + threadIdx.x;      // i < E/4
    if (i < N_EDGES / 4) {
        int4   r = ((const int4*)edge_row)[i];
        int4   c = ((const int4*)edge_col)[i];
        float4 v = ((const float4*)edge_val)[i];
        int p0 = atomicAdd(&g_cursor[r.x], 1);
        g_edge[p0] = make_uint2((uint32_t)c.x, __float_as_uint(v.x));
        int p1 = atomicAdd(&g_cursor[r.y], 1);
        g_edge[p1] = make_uint2((uint32_t)c.y, __float_as_uint(v.y));
        int p2 = atomicAdd(&g_cursor[r.z], 1);
        g_edge[p2] = make_uint2((uint32_t)c.z, __float_as_uint(v.z));
        int p3 = atomicAdd(&g_cursor[r.w], 1);
        g_edge[p3] = make_uint2((uint32_t)c.w, __float_as_uint(v.w));
    }
}

// ====================== fused W prep (all layers) + counts clear ============
// W[k*NC+n] -> img_hi[n][k], img_lo[n][k], rows padded to WROW.

__device__ __forceinline__ void w_split_store(const float* W, half* img,
                                              int NC, int idx) {
    int k = idx / NC;
    int n = idx % NC;
    float v = W[idx];
    half hi = __float2half_rn(v);
    half lo = __float2half_rn(v - __half2float(hi));
    img[n * WROW + k] = hi;
    img[NC * WROW + n * WROW + k] = lo;
}

__global__ void prep_all_kernel(const float* __restrict__ W1,
                                const float* __restrict__ W2,
                                const float* __restrict__ W3,
                                half* __restrict__ img1,
                                half* __restrict__ img2,
                                half* __restrict__ img3) {
    int idx = blockIdx.x * blockDim.x + threadIdx.x;    // < 16384
    for (int i = idx; i < N_NODES; i += gridDim.x * blockDim.x)
        g_counts[i] = 0;
    if (idx < 128 * 128) {
        w_split_store(W1, img1, 128, idx);
        w_split_store(W2, img2, 128, idx);
    }
    if (idx < 128 * 64)
        w_split_store(W3, img3, 64, idx);
}

// ============================ HMMA GEMM =====================================
// C[M,NC](fp16) = A[M,128] @ W[128,NC] via m16n8k16 f16->f32.
// AFP32: A fp32 -> hi/lo split, 3 terms. else A fp16 exact, 2 terms.

__device__ __forceinline__ void mma16816(float* d,
                                         uint32_t a0, uint32_t a1, uint32_t a2, uint32_t a3,
                                         uint32_t b0, uint32_t b1) {
    asm volatile(
        "mma.sync.aligned.m16n8k16.row.col.f32.f16.f16.f32 "
        "{%0,%1,%2,%3}, {%4,%5,%6,%7}, {%8,%9}, {%0,%1,%2,%3};"
        : "+f"(d[0]), "+f"(d[1]), "+f"(d[2]), "+f"(d[3])
        : "r"(a0), "r"(a1), "r"(a2), "r"(a3), "r"(b0), "r"(b1));
}

template <int NC, bool AFP32>
__global__ void __launch_bounds__(256, 1)
gemm_mma_kernel(const void* __restrict__ Aptr, const half* __restrict__ Wimg,
                half* __restrict__ C, int M) {
    extern __shared__ __align__(16) char smem_raw[];
    half* Wh = (half*)smem_raw;              // [NC][WROW]
    half* Wl = Wh + NC * WROW;
    half* Ah = Wl + NC * WROW;               // [128][WROW]
    half* Al = Ah + 128 * WROW;              // only used if AFP32

    const int tid = threadIdx.x;

    {   // W hi+lo images -> smem
        const uint4* src = (const uint4*)Wimg;
        uint4* dst = (uint4*)Wh;
        constexpr int n16 = 2 * NC * WROW * 2 / 16;
        #pragma unroll 4
        for (int i = tid; i < n16; i += 256) dst[i] = src[i];
    }

    {   // A tile -> smem (split if fp32)
        const int r  = tid >> 1;
        const int c0 = (tid & 1) * 64;
        const int gr = blockIdx.x * 128 + r;
        const bool valid = (gr < M);
        if (AFP32) {
            const float4* src = (const float4*)((const float*)Aptr + (size_t)gr * 128 + c0);
            #pragma unroll
            for (int j = 0; j < 16; j++) {
                float4 v = valid ? src[j] : make_float4(0.f, 0.f, 0.f, 0.f);
                half hx = __float2half_rn(v.x), hy = __float2half_rn(v.y);
                half hz = __float2half_rn(v.z), hw = __float2half_rn(v.w);
                half lx = __float2half_rn(v.x - __half2float(hx));
                half ly = __float2half_rn(v.y - __half2float(hy));
                half lz = __float2half_rn(v.z - __half2float(hz));
                half lw = __float2half_rn(v.w - __half2float(hw));
                int base = r * WROW + c0 + j * 4;
                *(half2*)&Ah[base]     = __halves2half2(hx, hy);
                *(half2*)&Ah[base + 2] = __halves2half2(hz, hw);
                *(half2*)&Al[base]     = __halves2half2(lx, ly);
                *(half2*)&Al[base + 2] = __halves2half2(lz, lw);
            }
        } else {
            const uint4* src = (const uint4*)((const half*)Aptr + (size_t)gr * 128 + c0);
            #pragma unroll
            for (int j = 0; j < 8; j++) {
                uint4 v = valid ? src[j] : make_uint4(0u, 0u, 0u, 0u);
                *(uint4*)&Ah[r * WROW + c0 + j * 8] = v;
            }
        }
    }
    __syncthreads();

    const int warp = tid >> 5;
    const int lane = tid & 31;
    const int qr = lane >> 2;
    const int qc = (lane & 3) * 2;
    const int mrow = warp * 16;

    constexpr int NT = NC / 8;
    float acc[NT][4];
    #pragma unroll
    for (int nt = 0; nt < NT; nt++)
        #pragma unroll
        for (int j = 0; j < 4; j++) acc[nt][j] = 0.f;

    #pragma unroll
    for (int ks = 0; ks < 8; ks++) {
        const int kb = ks * 16 + qc;
        const int ra = (mrow + qr) * WROW + kb;
        const int rb = (mrow + qr + 8) * WROW + kb;
        uint32_t ah0 = *(const uint32_t*)&Ah[ra];
        uint32_t ah1 = *(const uint32_t*)&Ah[rb];
        uint32_t ah2 = *(const uint32_t*)&Ah[ra + 8];
        uint32_t ah3 = *(const uint32_t*)&Ah[rb + 8];
        uint32_t al0 = 0, al1 = 0, al2 = 0, al3 = 0;
        if (AFP32) {
            al0 = *(const uint32_t*)&Al[ra];
            al1 = *(const uint32_t*)&Al[rb];
            al2 = *(const uint32_t*)&Al[ra + 8];
            al3 = *(const uint32_t*)&Al[rb + 8];
        }
        #pragma unroll
        for (int nt = 0; nt < NT; nt++) {
            const int nr = (nt * 8 + qr) * WROW + kb;
            uint32_t bh0 = *(const uint32_t*)&Wh[nr];
            uint32_t bh1 = *(const uint32_t*)&Wh[nr + 8];
            uint32_t bl0 = *(const uint32_t*)&Wl[nr];
            uint32_t bl1 = *(const uint32_t*)&Wl[nr + 8];
            mma16816(acc[nt], ah0, ah1, ah2, ah3, bh0, bh1);
            mma16816(acc[nt], ah0, ah1, ah2, ah3, bl0, bl1);
            if (AFP32)
                mma16816(acc[nt], al0, al1, al2, al3, bh0, bh1);
        }
    }

    const int grow = blockIdx.x * 128 + mrow + qr;
    #pragma unroll
    for (int nt = 0; nt < NT; nt++) {
        const int col = nt * 8 + qc;
        if (grow < M)
            *(half2*)&C[(size_t)grow * NC + col] =
                __floats2half2_rn(acc[nt][0], acc[nt][1]);
        if (grow + 8 < M)
            *(half2*)&C[(size_t)(grow + 8) * NC + col] =
                __floats2half2_rn(acc[nt][2], acc[nt][3]);
    }
}

// ================================ SpMM ======================================
// warp-per-row segmented sum over packed CSR edges; fp16 gathers, fp32 acc.
// OUT_HALF: write fp16 (hidden layers) else fp32 (final output).

template <int D, bool RELU, bool OUT_HALF>
__global__ void spmm_kernel(const half* __restrict__ S,
                            const float* __restrict__ bias,
                            void* __restrict__ outp, int N) {
    constexpr int F = D / 32;                 // halfs per lane (4 or 2)
    const int warp = (blockIdx.x * blockDim.x + threadIdx.x) >> 5;
    const int lane = threadIdx.x & 31;
    if (warp >= N) return;

    const int start = g_row_ptr[warp];
    const int end   = g_row_ptr[warp + 1];

    float acc[F];
    #pragma unroll
    for (int j = 0; j < F; j++) acc[j] = 0.0f;

    #pragma unroll 4
    for (int e = start; e < end; e++) {
        uint2 pr = __ldg(&g_edge[e]);
        int   c = (int)pr.x;
        float v = __uint_as_float(pr.y);
        if (F == 4) {
            uint2 p = *(const uint2*)&S[(size_t)c * D + lane * 4];
            float2 f0 = __half22float2(*(half2*)&p.x);
            float2 f1 = __half22float2(*(half2*)&p.y);
            acc[0] += v * f0.x; acc[1] += v * f0.y;
            acc[2] += v * f1.x; acc[3] += v * f1.y;
        } else {
            uint32_t p = *(const uint32_t*)&S[(size_t)c * D + lane * 2];
            float2 f0 = __half22float2(*(half2*)&p);
            acc[0] += v * f0.x; acc[1] += v * f0.y;
        }
    }

    #pragma unroll
    for (int j = 0; j < F; j++) {
        float r = acc[j] + __ldg(&bias[lane * F + j]);
        if (RELU) r = fmaxf(r, 0.0f);
        acc[j] = r;
    }

    if (OUT_HALF) {
        half* out = (half*)outp;
        if (F == 4) {
            half2 h0 = __floats2half2_rn(acc[0], acc[1]);
            half2 h1 = __floats2half2_rn(acc[2], acc[3]);
            *(uint2*)&out[(size_t)warp * D + lane * 4] =
                make_uint2(*(uint32_t*)&h0, *(uint32_t*)&h1);
        } else {
            half2 h0 = __floats2half2_rn(acc[0], acc[1]);
            *(uint32_t*)&out[(size_t)warp * D + lane * 2] = *(uint32_t*)&h0;
        }
    } else {
        float* out = (float*)outp;
        if (F == 4)
            *(float4*)&out[(size_t)warp * D + lane * 4] =
                make_float4(acc[0], acc[1], acc[2], acc[3]);
        else
            *(float2*)&out[(size_t)warp * D + lane * 2] =
                make_float2(acc[0], acc[1]);
    }
}

// ============================== launch =====================================

extern "C" void kernel_launch(void* const* d_in, const int* in_sizes, int n_in,
                              void* d_out, int out_size) {
    const float* x        = (const float*)d_in[0];
    const int*   edge_row = (const int*)  d_in[1];
    const int*   edge_col = (const int*)  d_in[2];
    const float* edge_val = (const float*)d_in[3];
    const float* W1       = (const float*)d_in[4];
    const float* b1       = (const float*)d_in[5];
    const float* W2       = (const float*)d_in[6];
    const float* b2       = (const float*)d_in[7];
    const float* W3       = (const float*)d_in[8];
    const float* b3       = (const float*)d_in[9];

    const int N = N_NODES;
    const int E = N_EDGES;

    half* support; cudaGetSymbolAddress((void**)&support, g_support);
    half* h;       cudaGetSymbolAddress((void**)&h, g_h);
    half* wimg;    cudaGetSymbolAddress((void**)&wimg, g_wimg);
    half* wimg1 = wimg;
    half* wimg2 = wimg + 2 * 128 * WROW;
    half* wimg3 = wimg + 4 * 128 * WROW;

    const int SMEM_L1 = (2 * 128 + 2 * 128) * WROW * 2;  // 139264 (fp32 A, 3-term)
    const int SMEM_L2 = (2 * 128 + 128) * WROW * 2;      // 104448 (fp16 A, 2-term)
    const int SMEM_L3 = (2 * 64 + 128) * WROW * 2;       //  69632
    cudaFuncSetAttribute((const void*)gemm_mma_kernel<128, true>,
                         cudaFuncAttributeMaxDynamicSharedMemorySize, SMEM_L1);
    cudaFuncSetAttribute((const void*)gemm_mma_kernel<128, false>,
                         cudaFuncAttributeMaxDynamicSharedMemorySize, SMEM_L2);
    cudaFuncSetAttribute((const void*)gemm_mma_kernel<64, false>,
                         cudaFuncAttributeMaxDynamicSharedMemorySize, SMEM_L3);

    // fused W prep + counts clear, then CSR build
    prep_all_kernel<<<64, 256>>>(W1, W2, W3, wimg1, wimg2, wimg3);
    hist_kernel<<<(E / 4 + 255) / 256, 256>>>(edge_row);
    scan_kernel<<<1, 1024>>>();
    scatter_kernel<<<(E / 4 + 255) / 256, 256>>>(edge_row, edge_col, edge_val);

    const int gemm_grid = (N + 127) / 128;   // 391
    const int spmm_grid = (N + 7) / 8;

    gemm_mma_kernel<128, true><<<gemm_grid, 256, SMEM_L1>>>(x, wimg1, support, N);
    spmm_kernel<128, true, true><<<spmm_grid, 256>>>(support, b1, h, N);

    gemm_mma_kernel<128, false><<<gemm_grid, 256, SMEM_L2>>>(h, wimg2, support, N);
    spmm_kernel<128, true, true><<<spmm_grid, 256>>>(support, b2, h, N);

    gemm_mma_kernel<64, false><<<gemm_grid, 256, SMEM_L3>>>(h, wimg3, support, N);
    spmm_kernel<64, false, false><<<spmm_grid, 256>>>(support, b3, d_out, N);
}

// round 7
// speedup vs baseline: 1.7135x; 1.0555x over previous
#include <cuda_runtime.h>
#include <cuda_fp16.h>
#include <cstdint>

#define N_NODES 50000
#define N_EDGES 800000
#define D_IN    128
#define D_HID   128
#define D_OUT   64

// -------- device scratch (allocation-free rule: __device__ globals) --------
__device__ __align__(16) half g_support[N_NODES * D_HID];  // GEMM out (fp16)
__device__ __align__(16) half g_h[N_NODES * D_HID];        // activations (fp16)
__device__ int   g_row_ptr[N_NODES + 1];
__device__ int   g_counts[N_NODES];
__device__ int   g_cursor[N_NODES];
__device__ __align__(16) uint2 g_edge[N_EDGES];            // (col, val) packed

// W images: fp16 hi/lo, W^T layout [n][k] with rows padded to 136 halfs.
#define WROW 136
__device__ __align__(16) half g_wimg[2 * 128 * WROW + 2 * 128 * WROW + 2 * 64 * WROW];

// ============================ CSR construction ==============================

__global__ void hist_kernel(const int* __restrict__ edge_row) {
    int i = blockIdx.x * blockDim.x + threadIdx.x;      // i < E/4
    if (i < N_EDGES / 4) {
        int4 r = ((const int4*)edge_row)[i];
        atomicAdd(&g_counts[r.x], 1);
        atomicAdd(&g_counts[r.y], 1);
        atomicAdd(&g_counts[r.z], 1);
        atomicAdd(&g_counts[r.w], 1);
    }
}

// single-block exclusive scan, int4 per thread; also seeds g_cursor = row_ptr
__global__ void scan_kernel() {
    __shared__ int warp_sums[32];
    __shared__ int carry_s;
    const int tid  = threadIdx.x;
    const int lane = tid & 31;
    const int wid  = tid >> 5;
    if (tid == 0) carry_s = 0;
    __syncthreads();
    const int4* c4 = (const int4*)g_counts;
    const int N4 = N_NODES / 4;
    for (int base = 0; base < N4; base += 1024) {
        int i = base + tid;
        int4 v = (i < N4) ? c4[i] : make_int4(0, 0, 0, 0);
        int s = v.x + v.y + v.z + v.w;
        int incl = s;
        #pragma unroll
        for (int off = 1; off < 32; off <<= 1) {
            int t = __shfl_up_sync(0xffffffffu, incl, off);
            if (lane >= off) incl += t;
        }
        if (lane == 31) warp_sums[wid] = incl;
        __syncthreads();
        if (wid == 0) {
            int ws = warp_sums[lane];
            int wincl = ws;
            #pragma unroll
            for (int off = 1; off < 32; off <<= 1) {
                int t = __shfl_up_sync(0xffffffffu, wincl, off);
                if (lane >= off) wincl += t;
            }
            warp_sums[lane] = wincl - ws;
        }
        __syncthreads();
        int carry = carry_s;
        int excl = carry + warp_sums[wid] + incl - s;
        if (i < N4) {
            int4 o;
            o.x = excl;
            o.y = excl + v.x;
            o.z = o.y + v.y;
            o.w = o.z + v.z;
            *(int4*)&g_row_ptr[4 * i] = o;
            *(int4*)&g_cursor[4 * i]  = o;
        }
        __syncthreads();
        if (tid == 1023) carry_s = carry + warp_sums[31] + incl;
        __syncthreads();
    }
    if (tid == 0) g_row_ptr[N_NODES] = carry_s;
}

__global__ void scatter_kernel(const int* __restrict__ edge_row,
                               const int* __restrict__ edge_col,
                               const float* __restrict__ edge_val) {
    int i = blockIdx.x * blockDim.x + threadIdx.x;      // i < E/4
    if (i < N_EDGES / 4) {
        int4   r = ((const int4*)edge_row)[i];
        int4   c = ((const int4*)edge_col)[i];
        float4 v = ((const float4*)edge_val)[i];
        int p0 = atomicAdd(&g_cursor[r.x], 1);
        g_edge[p0] = make_uint2((uint32_t)c.x, __float_as_uint(v.x));
        int p1 = atomicAdd(&g_cursor[r.y], 1);
        g_edge[p1] = make_uint2((uint32_t)c.y, __float_as_uint(v.y));
        int p2 = atomicAdd(&g_cursor[r.z], 1);
        g_edge[p2] = make_uint2((uint32_t)c.z, __float_as_uint(v.z));
        int p3 = atomicAdd(&g_cursor[r.w], 1);
        g_edge[p3] = make_uint2((uint32_t)c.w, __float_as_uint(v.w));
    }
}

// ====================== fused W prep (all layers) + counts clear ============

__device__ __forceinline__ void w_split_store(const float* W, half* img,
                                              int NC, int idx) {
    int k = idx / NC;
    int n = idx % NC;
    float v = W[idx];
    half hi = __float2half_rn(v);
    half lo = __float2half_rn(v - __half2float(hi));
    img[n * WROW + k] = hi;
    img[NC * WROW + n * WROW + k] = lo;
}

__global__ void prep_all_kernel(const float* __restrict__ W1,
                                const float* __restrict__ W2,
                                const float* __restrict__ W3,
                                half* __restrict__ img1,
                                half* __restrict__ img2,
                                half* __restrict__ img3) {
    int idx = blockIdx.x * blockDim.x + threadIdx.x;    // < 16384
    for (int i = idx; i < N_NODES; i += gridDim.x * blockDim.x)
        g_counts[i] = 0;
    if (idx < 128 * 128) {
        w_split_store(W1, img1, 128, idx);
        w_split_store(W2, img2, 128, idx);
    }
    if (idx < 128 * 64)
        w_split_store(W3, img3, 64, idx);
}

// ============================ HMMA GEMM =====================================

__device__ __forceinline__ void mma16816(float* d,
                                         uint32_t a0, uint32_t a1, uint32_t a2, uint32_t a3,
                                         uint32_t b0, uint32_t b1) {
    asm volatile(
        "mma.sync.aligned.m16n8k16.row.col.f32.f16.f16.f32 "
        "{%0,%1,%2,%3}, {%4,%5,%6,%7}, {%8,%9}, {%0,%1,%2,%3};"
        : "+f"(d[0]), "+f"(d[1]), "+f"(d[2]), "+f"(d[3])
        : "r"(a0), "r"(a1), "r"(a2), "r"(a3), "r"(b0), "r"(b1));
}

template <int NC, bool AFP32>
__global__ void __launch_bounds__(256, 1)
gemm_mma_kernel(const void* __restrict__ Aptr, const half* __restrict__ Wimg,
                half* __restrict__ C, int M) {
    extern __shared__ __align__(16) char smem_raw[];
    half* Wh = (half*)smem_raw;              // [NC][WROW]
    half* Wl = Wh + NC * WROW;
    half* Ah = Wl + NC * WROW;               // [128][WROW]
    half* Al = Ah + 128 * WROW;              // only used if AFP32

    const int tid = threadIdx.x;

    {
        const uint4* src = (const uint4*)Wimg;
        uint4* dst = (uint4*)Wh;
        constexpr int n16 = 2 * NC * WROW * 2 / 16;
        #pragma unroll 4
        for (int i = tid; i < n16; i += 256) dst[i] = src[i];
    }

    {
        const int r  = tid >> 1;
        const int c0 = (tid & 1) * 64;
        const int gr = blockIdx.x * 128 + r;
        const bool valid = (gr < M);
        if (AFP32) {
            const float4* src = (const float4*)((const float*)Aptr + (size_t)gr * 128 + c0);
            #pragma unroll
            for (int j = 0; j < 16; j++) {
                float4 v = valid ? src[j] : make_float4(0.f, 0.f, 0.f, 0.f);
                half hx = __float2half_rn(v.x), hy = __float2half_rn(v.y);
                half hz = __float2half_rn(v.z), hw = __float2half_rn(v.w);
                half lx = __float2half_rn(v.x - __half2float(hx));
                half ly = __float2half_rn(v.y - __half2float(hy));
                half lz = __float2half_rn(v.z - __half2float(hz));
                half lw = __float2half_rn(v.w - __half2float(hw));
                int base = r * WROW + c0 + j * 4;
                *(half2*)&Ah[base]     = __halves2half2(hx, hy);
                *(half2*)&Ah[base + 2] = __halves2half2(hz, hw);
                *(half2*)&Al[base]     = __halves2half2(lx, ly);
                *(half2*)&Al[base + 2] = __halves2half2(lz, lw);
            }
        } else {
            const uint4* src = (const uint4*)((const half*)Aptr + (size_t)gr * 128 + c0);
            #pragma unroll
            for (int j = 0; j < 8; j++) {
                uint4 v = valid ? src[j] : make_uint4(0u, 0u, 0u, 0u);
                *(uint4*)&Ah[r * WROW + c0 + j * 8] = v;
            }
        }
    }
    __syncthreads();

    const int warp = tid >> 5;
    const int lane = tid & 31;
    const int qr = lane >> 2;
    const int qc = (lane & 3) * 2;
    const int mrow = warp * 16;

    constexpr int NT = NC / 8;
    float acc[NT][4];
    #pragma unroll
    for (int nt = 0; nt < NT; nt++)
        #pragma unroll
        for (int j = 0; j < 4; j++) acc[nt][j] = 0.f;

    #pragma unroll
    for (int ks = 0; ks < 8; ks++) {
        const int kb = ks * 16 + qc;
        const int ra = (mrow + qr) * WROW + kb;
        const int rb = (mrow + qr + 8) * WROW + kb;
        uint32_t ah0 = *(const uint32_t*)&Ah[ra];
        uint32_t ah1 = *(const uint32_t*)&Ah[rb];
        uint32_t ah2 = *(const uint32_t*)&Ah[ra + 8];
        uint32_t ah3 = *(const uint32_t*)&Ah[rb + 8];
        uint32_t al0 = 0, al1 = 0, al2 = 0, al3 = 0;
        if (AFP32) {
            al0 = *(const uint32_t*)&Al[ra];
            al1 = *(const uint32_t*)&Al[rb];
            al2 = *(const uint32_t*)&Al[ra + 8];
            al3 = *(const uint32_t*)&Al[rb + 8];
        }
        #pragma unroll
        for (int nt = 0; nt < NT; nt++) {
            const int nr = (nt * 8 + qr) * WROW + kb;
            uint32_t bh0 = *(const uint32_t*)&Wh[nr];
            uint32_t bh1 = *(const uint32_t*)&Wh[nr + 8];
            uint32_t bl0 = *(const uint32_t*)&Wl[nr];
            uint32_t bl1 = *(const uint32_t*)&Wl[nr + 8];
            mma16816(acc[nt], ah0, ah1, ah2, ah3, bh0, bh1);
            mma16816(acc[nt], ah0, ah1, ah2, ah3, bl0, bl1);
            if (AFP32)
                mma16816(acc[nt], al0, al1, al2, al3, bh0, bh1);
        }
    }

    const int grow = blockIdx.x * 128 + mrow + qr;
    #pragma unroll
    for (int nt = 0; nt < NT; nt++) {
        const int col = nt * 8 + qc;
        if (grow < M)
            *(half2*)&C[(size_t)grow * NC + col] =
                __floats2half2_rn(acc[nt][0], acc[nt][1]);
        if (grow + 8 < M)
            *(half2*)&C[(size_t)(grow + 8) * NC + col] =
                __floats2half2_rn(acc[nt][2], acc[nt][3]);
    }
}

// ================================ SpMM ======================================
// warp-per-row segmented sum; 2-way unrolled edge loop for gather MLP.

template <int D, bool RELU, bool OUT_HALF>
__global__ void spmm_kernel(const half* __restrict__ S,
                            const float* __restrict__ bias,
                            void* __restrict__ outp, int N) {
    constexpr int F = D / 32;                 // halfs per lane (4 or 2)
    const int warp = (blockIdx.x * blockDim.x + threadIdx.x) >> 5;
    const int lane = threadIdx.x & 31;
    if (warp >= N) return;

    const int start = g_row_ptr[warp];
    const int end   = g_row_ptr[warp + 1];

    float acc0[F], acc1[F];
    #pragma unroll
    for (int j = 0; j < F; j++) { acc0[j] = 0.0f; acc1[j] = 0.0f; }

    int e = start;
    #pragma unroll 2
    for (; e + 1 < end; e += 2) {
        uint2 pr0 = __ldg(&g_edge[e]);
        uint2 pr1 = __ldg(&g_edge[e + 1]);
        float v0 = __uint_as_float(pr0.y);
        float v1 = __uint_as_float(pr1.y);
        if (F == 4) {
            uint2 p0 = *(const uint2*)&S[(size_t)(int)pr0.x * D + lane * 4];
            uint2 p1 = *(const uint2*)&S[(size_t)(int)pr1.x * D + lane * 4];
            float2 a0 = __half22float2(*(half2*)&p0.x);
            float2 b0 = __half22float2(*(half2*)&p0.y);
            float2 a1 = __half22float2(*(half2*)&p1.x);
            float2 b1 = __half22float2(*(half2*)&p1.y);
            acc0[0] += v0 * a0.x; acc0[1] += v0 * a0.y;
            acc0[2] += v0 * b0.x; acc0[3] += v0 * b0.y;
            acc1[0] += v1 * a1.x; acc1[1] += v1 * a1.y;
            acc1[2] += v1 * b1.x; acc1[3] += v1 * b1.y;
        } else {
            uint32_t p0 = *(const uint32_t*)&S[(size_t)(int)pr0.x * D + lane * 2];
            uint32_t p1 = *(const uint32_t*)&S[(size_t)(int)pr1.x * D + lane * 2];
            float2 a0 = __half22float2(*(half2*)&p0);
            float2 a1 = __half22float2(*(half2*)&p1);
            acc0[0] += v0 * a0.x; acc0[1] += v0 * a0.y;
            acc1[0] += v1 * a1.x; acc1[1] += v1 * a1.y;
        }
    }
    if (e < end) {
        uint2 pr = __ldg(&g_edge[e]);
        float v = __uint_as_float(pr.y);
        if (F == 4) {
            uint2 p = *(const uint2*)&S[(size_t)(int)pr.x * D + lane * 4];
            float2 a = __half22float2(*(half2*)&p.x);
            float2 b = __half22float2(*(half2*)&p.y);
            acc0[0] += v * a.x; acc0[1] += v * a.y;
            acc0[2] += v * b.x; acc0[3] += v * b.y;
        } else {
            uint32_t p = *(const uint32_t*)&S[(size_t)(int)pr.x * D + lane * 2];
            float2 a = __half22float2(*(half2*)&p);
            acc0[0] += v * a.x; acc0[1] += v * a.y;
        }
    }

    float acc[F];
    #pragma unroll
    for (int j = 0; j < F; j++) {
        float r = acc0[j] + acc1[j] + __ldg(&bias[lane * F + j]);
        if (RELU) r = fmaxf(r, 0.0f);
        acc[j] = r;
    }

    if (OUT_HALF) {
        half* out = (half*)outp;
        if (F == 4) {
            half2 h0 = __floats2half2_rn(acc[0], acc[1]);
            half2 h1 = __floats2half2_rn(acc[2], acc[3]);
            *(uint2*)&out[(size_t)warp * D + lane * 4] =
                make_uint2(*(uint32_t*)&h0, *(uint32_t*)&h1);
        } else {
            half2 h0 = __floats2half2_rn(acc[0], acc[1]);
            *(uint32_t*)&out[(size_t)warp * D + lane * 2] = *(uint32_t*)&h0;
        }
    } else {
        float* out = (float*)outp;
        if (F == 4)
            *(float4*)&out[(size_t)warp * D + lane * 4] =
                make_float4(acc[0], acc[1], acc[2], acc[3]);
        else
            *(float2*)&out[(size_t)warp * D + lane * 2] =
                make_float2(acc[0], acc[1]);
    }
}

// ============================== launch =====================================

extern "C" void kernel_launch(void* const* d_in, const int* in_sizes, int n_in,
                              void* d_out, int out_size) {
    const float* x        = (const float*)d_in[0];
    const int*   edge_row = (const int*)  d_in[1];
    const int*   edge_col = (const int*)  d_in[2];
    const float* edge_val = (const float*)d_in[3];
    const float* W1       = (const float*)d_in[4];
    const float* b1       = (const float*)d_in[5];
    const float* W2       = (const float*)d_in[6];
    const float* b2       = (const float*)d_in[7];
    const float* W3       = (const float*)d_in[8];
    const float* b3       = (const float*)d_in[9];

    const int N = N_NODES;
    const int E = N_EDGES;

    half* support; cudaGetSymbolAddress((void**)&support, g_support);
    half* h;       cudaGetSymbolAddress((void**)&h, g_h);
    half* wimg;    cudaGetSymbolAddress((void**)&wimg, g_wimg);
    half* wimg1 = wimg;
    half* wimg2 = wimg + 2 * 128 * WROW;
    half* wimg3 = wimg + 4 * 128 * WROW;

    const int SMEM_L1 = (2 * 128 + 2 * 128) * WROW * 2;  // 139264
    const int SMEM_L2 = (2 * 128 + 128) * WROW * 2;      // 104448
    const int SMEM_L3 = (2 * 64 + 128) * WROW * 2;       //  69632
    cudaFuncSetAttribute((const void*)gemm_mma_kernel<128, true>,
                         cudaFuncAttributeMaxDynamicSharedMemorySize, SMEM_L1);
    cudaFuncSetAttribute((const void*)gemm_mma_kernel<128, false>,
                         cudaFuncAttributeMaxDynamicSharedMemorySize, SMEM_L2);
    cudaFuncSetAttribute((const void*)gemm_mma_kernel<64, false>,
                         cudaFuncAttributeMaxDynamicSharedMemorySize, SMEM_L3);

    // side stream + events for CSR/GEMM1 overlap (created per call; not
    // destroyed — kernel_launch runs only a few times and destroying a
    // forked stream during capture can invalidate the capture).
    cudaStream_t s2;
    cudaEvent_t ev_fork, ev_join;
    cudaStreamCreateWithFlags(&s2, cudaStreamNonBlocking);
    cudaEventCreateWithFlags(&ev_fork, cudaEventDisableTiming);
    cudaEventCreateWithFlags(&ev_join, cudaEventDisableTiming);

    // prep (clears counts, builds W images) on main stream
    prep_all_kernel<<<64, 256>>>(W1, W2, W3, wimg1, wimg2, wimg3);

    // fork: CSR chain on s2, GEMM1 on main stream
    cudaEventRecord(ev_fork, 0);
    cudaStreamWaitEvent(s2, ev_fork, 0);
    hist_kernel<<<(E / 4 + 255) / 256, 256, 0, s2>>>(edge_row);
    scan_kernel<<<1, 1024, 0, s2>>>();
    scatter_kernel<<<(E / 4 + 255) / 256, 256, 0, s2>>>(edge_row, edge_col, edge_val);
    cudaEventRecord(ev_join, s2);

    const int gemm_grid = (N + 127) / 128;   // 391
    const int spmm_grid = (N + 7) / 8;

    gemm_mma_kernel<128, true><<<gemm_grid, 256, SMEM_L1>>>(x, wimg1, support, N);

    // join: SpMM1 needs both GEMM1 (main) and CSR (s2)
    cudaStreamWaitEvent(0, ev_join, 0);

    spmm_kernel<128, true, true><<<spmm_grid, 256>>>(support, b1, h, N);

    gemm_mma_kernel<128, false><<<gemm_grid, 256, SMEM_L2>>>(h, wimg2, support, N);
    spmm_kernel<128, true, true><<<spmm_grid, 256>>>(support, b2, h, N);

    gemm_mma_kernel<64, false><<<gemm_grid, 256, SMEM_L3>>>(h, wimg3, support, N);
    spmm_kernel<64, false, false><<<spmm_grid, 256>>>(support, b3, d_out, N);
}